// round 4
// baseline (speedup 1.0000x reference)
#include <cuda_runtime.h>
#include <math.h>

#define BATCH 64
#define NTOT  65536
#define DIM   1024
#define CHUNK 256
#define MAX_CHUNKS 320   // NTOT/CHUNK + BATCH (upper bound on sum of ceils)

// ---------------- device scratch (static, no allocation) ----------------
__device__ float g_vpart[8 * BATCH * DIM];        // h-split partials of v = d @ W
__device__ float g_v[BATCH * DIM];                // v[b][m]
__device__ int   g_chunk_seg[MAX_CHUNKS];
__device__ int   g_chunk_start[MAX_CHUNKS];
__device__ int   g_chunk_cnt[MAX_CHUNKS];
__device__ int   g_seg_chunk_start[BATCH];
__device__ int   g_seg_chunk_cnt[BATCH];
__device__ float g_part_m[MAX_CHUNKS];
__device__ float g_part_z[MAX_CHUNKS];
__device__ float4 g_part_acc[MAX_CHUNKS * (DIM / 4)];

// ---------------- setup: prefix sums over ragged lengths -> chunk table ----------------
// Handles the harness delivering tree_node_num_lst as EITHER int32 or int64.
// Detection reads only the first 256 bytes (valid in both layouts): for int64
// little-endian, the high word of element 0 (view32[1]) is 0; for int32 it is
// a length >= 1.
__global__ void setup_kernel(const int* __restrict__ lens_raw) {
    if (threadIdx.x == 0 && blockIdx.x == 0) {
        const long long* lens64 = (const long long*)lens_raw;
        bool is64 = (lens_raw[1] == 0);
        int c = 0, off = 0;
        for (int b = 0; b < BATCH; b++) {
            int len = is64 ? (int)lens64[b] : lens_raw[b];
            int nck = (len + CHUNK - 1) / CHUNK;
            g_seg_chunk_start[b] = c;
            g_seg_chunk_cnt[b]   = nck;
            for (int k = 0; k < nck; k++) {
                g_chunk_seg[c]   = b;
                g_chunk_start[c] = off + k * CHUNK;
                int rem = len - k * CHUNK;
                g_chunk_cnt[c]   = rem < CHUNK ? rem : CHUNK;
                c++;
            }
            off += len;
        }
        for (; c < MAX_CHUNKS; c++) g_chunk_cnt[c] = 0;
    }
}

// ---------------- v projection: v[b][m] = sum_h d[b][h] * W[h][m] ----------------
// grid (4 m-tiles, 4 b-tiles, 8 h-splits), block 256. Deterministic split-K via g_vpart.
__global__ void vproj_kernel(const float* __restrict__ dstate, const float* __restrict__ W) {
    __shared__ float dsh[16][128];
    int m  = blockIdx.x * 256 + threadIdx.x;
    int b0 = blockIdx.y * 16;
    int h0 = blockIdx.z * 128;

    for (int i = threadIdx.x; i < 16 * 128; i += 256) {
        int bi = i >> 7, hh = i & 127;
        dsh[bi][hh] = dstate[(b0 + bi) * DIM + h0 + hh];
    }
    __syncthreads();

    float acc[16];
#pragma unroll
    for (int i = 0; i < 16; i++) acc[i] = 0.f;

    for (int hh = 0; hh < 128; hh++) {
        float w = W[(size_t)(h0 + hh) * DIM + m];
#pragma unroll
        for (int i = 0; i < 16; i++) acc[i] = fmaf(dsh[i][hh], w, acc[i]);
    }

    float* outp = g_vpart + (size_t)blockIdx.z * (BATCH * DIM);
#pragma unroll
    for (int i = 0; i < 16; i++) outp[(b0 + i) * DIM + m] = acc[i];
}

__global__ void vreduce_kernel() {
    int i = blockIdx.x * blockDim.x + threadIdx.x;   // 64K threads
    float s = 0.f;
#pragma unroll
    for (int p = 0; p < 8; p++) s += g_vpart[p * BATCH * DIM + i];
    g_v[i] = s;
}

// ---------------- phase 1: per-chunk online softmax + weighted row accumulation ----------------
// One CTA per chunk; warp-per-node; lane owns 32 elements (8 x float4).
__global__ void __launch_bounds__(256, 2) phase1_kernel(const float* __restrict__ mem) {
    __shared__ float4 s_acc[8][256];   // 32 KB: per-warp accumulators
    __shared__ float  s_m[8], s_z[8];

    int c   = blockIdx.x;
    int cnt = g_chunk_cnt[c];
    if (cnt == 0) return;
    int seg   = g_chunk_seg[c];
    int start = g_chunk_start[c];
    int warp  = threadIdx.x >> 5;
    int lane  = threadIdx.x & 31;

    // v row for this segment, register-resident
    const float4* vp = (const float4*)(g_v + seg * DIM);
    float4 v[8];
#pragma unroll
    for (int j = 0; j < 8; j++) v[j] = vp[j * 32 + lane];

    float m = -INFINITY, z = 0.f;
    float4 acc[8];
#pragma unroll
    for (int j = 0; j < 8; j++) acc[j] = make_float4(0.f, 0.f, 0.f, 0.f);

    for (int i = warp; i < cnt; i += 8) {
        const float4* row = (const float4*)(mem + (size_t)(start + i) * DIM);
        float4 r[8];
#pragma unroll
        for (int j = 0; j < 8; j++) r[j] = row[j * 32 + lane];

        float s = 0.f;
#pragma unroll
        for (int j = 0; j < 8; j++)
            s += r[j].x * v[j].x + r[j].y * v[j].y + r[j].z * v[j].z + r[j].w * v[j].w;
#pragma unroll
        for (int o = 16; o > 0; o >>= 1) s += __shfl_xor_sync(0xffffffffu, s, o);

        if (s > m) {
            // new running max: rescale accumulator (exp(-inf)=0 handles first node)
            float sc = __expf(m - s);
            z = z * sc + 1.f;
#pragma unroll
            for (int j = 0; j < 8; j++) {
                acc[j].x = acc[j].x * sc + r[j].x;
                acc[j].y = acc[j].y * sc + r[j].y;
                acc[j].z = acc[j].z * sc + r[j].z;
                acc[j].w = acc[j].w * sc + r[j].w;
            }
            m = s;
        } else {
            float w8 = __expf(s - m);
            z += w8;
#pragma unroll
            for (int j = 0; j < 8; j++) {
                acc[j].x = fmaf(w8, r[j].x, acc[j].x);
                acc[j].y = fmaf(w8, r[j].y, acc[j].y);
                acc[j].z = fmaf(w8, r[j].z, acc[j].z);
                acc[j].w = fmaf(w8, r[j].w, acc[j].w);
            }
        }
    }

    // combine 8 warp-local accumulators -> chunk partial
#pragma unroll
    for (int j = 0; j < 8; j++) s_acc[warp][j * 32 + lane] = acc[j];
    if (lane == 0) { s_m[warp] = m; s_z[warp] = z; }
    __syncthreads();

    float m_b = -INFINITY;
#pragma unroll
    for (int w = 0; w < 8; w++) m_b = fmaxf(m_b, s_m[w]);

    int t = threadIdx.x;
    float  z_b = 0.f;
    float4 a   = make_float4(0.f, 0.f, 0.f, 0.f);
#pragma unroll
    for (int w = 0; w < 8; w++) {
        float mw = s_m[w];
        float sc = (mw == -INFINITY) ? 0.f : __expf(mw - m_b);  // idle warp -> 0
        float4 aw = s_acc[w][t];
        a.x = fmaf(sc, aw.x, a.x);
        a.y = fmaf(sc, aw.y, a.y);
        a.z = fmaf(sc, aw.z, a.z);
        a.w = fmaf(sc, aw.w, a.w);
        z_b = fmaf(sc, s_z[w], z_b);
    }
    g_part_acc[c * (DIM / 4) + t] = a;
    if (t == 0) { g_part_m[c] = m_b; g_part_z[c] = z_b; }
}

// ---------------- phase 2: combine chunk partials per segment, normalize ----------------
__global__ void phase2_kernel(float* __restrict__ out) {
    int b  = blockIdx.x;
    int cs = g_seg_chunk_start[b];
    int cc = g_seg_chunk_cnt[b];
    int t  = threadIdx.x;

    if (cc == 0) {   // defensive: empty segment -> zeros, not NaN
        ((float4*)out)[b * (DIM / 4) + t] = make_float4(0.f, 0.f, 0.f, 0.f);
        return;
    }

    float m_g = -INFINITY;
    for (int ci = 0; ci < cc; ci++) m_g = fmaxf(m_g, g_part_m[cs + ci]);

    float  z = 0.f;
    float4 a = make_float4(0.f, 0.f, 0.f, 0.f);
    for (int ci = 0; ci < cc; ci++) {
        float sc = __expf(g_part_m[cs + ci] - m_g);
        float4 p = g_part_acc[(cs + ci) * (DIM / 4) + t];
        a.x = fmaf(sc, p.x, a.x);
        a.y = fmaf(sc, p.y, a.y);
        a.z = fmaf(sc, p.z, a.z);
        a.w = fmaf(sc, p.w, a.w);
        z = fmaf(sc, g_part_z[cs + ci], z);
    }
    float inv = 1.f / z;
    ((float4*)out)[b * (DIM / 4) + t] =
        make_float4(a.x * inv, a.y * inv, a.z * inv, a.w * inv);
}

// ---------------- launch ----------------
extern "C" void kernel_launch(void* const* d_in, const int* in_sizes, int n_in,
                              void* d_out, int out_size) {
    // Identify inputs by element count (ordering-proof):
    //   memory_bank 65536*1024 = 67108864, decoder_state 64*1024 = 65536,
    //   W 1024*1024 = 1048576, tree_node_num_lst = 64.
    const float* mem    = nullptr;
    const float* dstate = nullptr;
    const float* W      = nullptr;
    const int*   lens   = nullptr;
    for (int i = 0; i < n_in; i++) {
        switch (in_sizes[i]) {
            case 67108864: mem    = (const float*)d_in[i]; break;
            case 65536:    dstate = (const float*)d_in[i]; break;
            case 1048576:  W      = (const float*)d_in[i]; break;
            case 64:       lens   = (const int*)d_in[i];   break;
        }
    }
    float* out = (float*)d_out;

    setup_kernel<<<1, 32>>>(lens);
    vproj_kernel<<<dim3(4, 4, 8), 256>>>(dstate, W);
    vreduce_kernel<<<256, 256>>>();
    phase1_kernel<<<MAX_CHUNKS, 256>>>(mem);
    phase2_kernel<<<BATCH, 256>>>(out);
}

// round 5
// speedup vs baseline: 1.2152x; 1.2152x over previous
#include <cuda_runtime.h>
#include <math.h>

#define BATCH 64
#define NTOT  65536
#define DIM   1024
#define CHUNK 128
#define MAX_CHUNKS 576   // NTOT/CHUNK + BATCH
#define NSPLIT 16        // vproj split-K factor
#define P1_GRID 296      // persistent CTAs for phase1 (2 per SM on 148 SMs)

// ---------------- device scratch (static, no allocation) ----------------
__device__ float g_vpart[NSPLIT * BATCH * DIM];   // h-split partials of v = d @ W
__device__ float g_v[BATCH * DIM];                // v[b][m]
__device__ int   g_chunk_seg[MAX_CHUNKS];
__device__ int   g_chunk_start[MAX_CHUNKS];
__device__ int   g_chunk_cnt[MAX_CHUNKS];
__device__ int   g_seg_chunk_start[BATCH];
__device__ int   g_seg_chunk_cnt[BATCH];
__device__ float g_part_m[MAX_CHUNKS];
__device__ float g_part_z[MAX_CHUNKS];
__device__ float4 g_part_acc[MAX_CHUNKS * (DIM / 4)];

// ---------------- setup: parallel prefix over ragged lengths -> chunk table ----------------
// Handles lens delivered as int32 or int64 (harness downcasts int64 per stub dtypes;
// detection: int64 little-endian high word of elem 0 is 0, int32 elem 1 is a len >= 1).
__global__ void setup_kernel(const int* __restrict__ lens_raw) {
    __shared__ int s_len[BATCH];
    __shared__ int s_node_off[BATCH];   // exclusive prefix of node counts
    __shared__ int s_chunk_off[BATCH];  // exclusive prefix of chunk counts

    int b = threadIdx.x;   // 64 threads
    const long long* lens64 = (const long long*)lens_raw;
    bool is64 = (lens_raw[1] == 0);
    int len = is64 ? (int)lens64[b] : lens_raw[b];
    s_len[b] = len;
    __syncthreads();

    if (b == 0) {   // tiny serial scan over 64 entries (shared-mem, fast)
        int noff = 0, coff = 0;
        for (int i = 0; i < BATCH; i++) {
            s_node_off[i]  = noff;
            s_chunk_off[i] = coff;
            noff += s_len[i];
            coff += (s_len[i] + CHUNK - 1) / CHUNK;
        }
    }
    __syncthreads();

    int nck = (len + CHUNK - 1) / CHUNK;
    int cs  = s_chunk_off[b];
    g_seg_chunk_start[b] = cs;
    g_seg_chunk_cnt[b]   = nck;
    for (int k = 0; k < nck; k++) {
        g_chunk_seg[cs + k]   = b;
        g_chunk_start[cs + k] = s_node_off[b] + k * CHUNK;
        int rem = len - k * CHUNK;
        g_chunk_cnt[cs + k]   = rem < CHUNK ? rem : CHUNK;
    }
    // zero-fill the tail of the table (distributed across threads)
    int total = s_chunk_off[BATCH - 1] +
                (s_len[BATCH - 1] + CHUNK - 1) / CHUNK;
    for (int c = total + b; c < MAX_CHUNKS; c += BATCH) g_chunk_cnt[c] = 0;
}

// ---------------- v projection: v[b][m] = sum_h d[b][h] * W[h][m] ----------------
// grid (4 m-tiles, 4 b-tiles, 16 h-splits) = 256 blocks, block 256. Deterministic split-K.
__global__ void vproj_kernel(const float* __restrict__ dstate, const float* __restrict__ W) {
    __shared__ float dsh[16][64];
    int m  = blockIdx.x * 256 + threadIdx.x;
    int b0 = blockIdx.y * 16;
    int h0 = blockIdx.z * 64;

    for (int i = threadIdx.x; i < 16 * 64; i += 256) {
        int bi = i >> 6, hh = i & 63;
        dsh[bi][hh] = dstate[(b0 + bi) * DIM + h0 + hh];
    }
    __syncthreads();

    float acc[16];
#pragma unroll
    for (int i = 0; i < 16; i++) acc[i] = 0.f;

#pragma unroll 4
    for (int hh = 0; hh < 64; hh++) {
        float w = W[(size_t)(h0 + hh) * DIM + m];
#pragma unroll
        for (int i = 0; i < 16; i++) acc[i] = fmaf(dsh[i][hh], w, acc[i]);
    }

    float* outp = g_vpart + (size_t)blockIdx.z * (BATCH * DIM);
#pragma unroll
    for (int i = 0; i < 16; i++) outp[(b0 + i) * DIM + m] = acc[i];
}

__global__ void vreduce_kernel() {
    int i = blockIdx.x * blockDim.x + threadIdx.x;   // 64K threads
    float s = 0.f;
#pragma unroll
    for (int p = 0; p < NSPLIT; p++) s += g_vpart[p * BATCH * DIM + i];
    g_v[i] = s;
}

// ---------------- phase 1: persistent CTAs, per-chunk online softmax ----------------
// Grid-stride over the chunk table for perfect balance. Warp-per-node; lane owns
// 32 elements (8 x float4).
__global__ void __launch_bounds__(256, 2) phase1_kernel(const float* __restrict__ mem) {
    __shared__ float4 s_acc[8][256];   // 32 KB: per-warp accumulators
    __shared__ float  s_m[8], s_z[8];

    int warp = threadIdx.x >> 5;
    int lane = threadIdx.x & 31;
    int t    = threadIdx.x;

    for (int c = blockIdx.x; c < MAX_CHUNKS; c += P1_GRID) {
        int cnt = g_chunk_cnt[c];           // uniform per CTA
        if (cnt == 0) continue;
        int seg   = g_chunk_seg[c];
        int start = g_chunk_start[c];

        // v row for this segment (L2-hot), register-resident
        const float4* vp = (const float4*)(g_v + seg * DIM);
        float4 v[8];
#pragma unroll
        for (int j = 0; j < 8; j++) v[j] = vp[j * 32 + lane];

        float m = -INFINITY, z = 0.f;
        float4 acc[8];
#pragma unroll
        for (int j = 0; j < 8; j++) acc[j] = make_float4(0.f, 0.f, 0.f, 0.f);

        for (int i = warp; i < cnt; i += 8) {
            const float4* row = (const float4*)(mem + (size_t)(start + i) * DIM);
            float4 r[8];
#pragma unroll
            for (int j = 0; j < 8; j++) r[j] = row[j * 32 + lane];

            float s = 0.f;
#pragma unroll
            for (int j = 0; j < 8; j++)
                s += r[j].x * v[j].x + r[j].y * v[j].y + r[j].z * v[j].z + r[j].w * v[j].w;
#pragma unroll
            for (int o = 16; o > 0; o >>= 1) s += __shfl_xor_sync(0xffffffffu, s, o);

            if (s > m) {
                float sc = __expf(m - s);   // exp(-inf)=0 handles first node
                z = z * sc + 1.f;
#pragma unroll
                for (int j = 0; j < 8; j++) {
                    acc[j].x = acc[j].x * sc + r[j].x;
                    acc[j].y = acc[j].y * sc + r[j].y;
                    acc[j].z = acc[j].z * sc + r[j].z;
                    acc[j].w = acc[j].w * sc + r[j].w;
                }
                m = s;
            } else {
                float w8 = __expf(s - m);
                z += w8;
#pragma unroll
                for (int j = 0; j < 8; j++) {
                    acc[j].x = fmaf(w8, r[j].x, acc[j].x);
                    acc[j].y = fmaf(w8, r[j].y, acc[j].y);
                    acc[j].z = fmaf(w8, r[j].z, acc[j].z);
                    acc[j].w = fmaf(w8, r[j].w, acc[j].w);
                }
            }
        }

        // combine 8 warp-local accumulators -> chunk partial
#pragma unroll
        for (int j = 0; j < 8; j++) s_acc[warp][j * 32 + lane] = acc[j];
        if (lane == 0) { s_m[warp] = m; s_z[warp] = z; }
        __syncthreads();

        float m_b = -INFINITY;
#pragma unroll
        for (int w = 0; w < 8; w++) m_b = fmaxf(m_b, s_m[w]);

        float  z_b = 0.f;
        float4 a   = make_float4(0.f, 0.f, 0.f, 0.f);
#pragma unroll
        for (int w = 0; w < 8; w++) {
            float mw = s_m[w];
            float sc = (mw == -INFINITY) ? 0.f : __expf(mw - m_b);  // idle warp -> 0
            float4 aw = s_acc[w][t];
            a.x = fmaf(sc, aw.x, a.x);
            a.y = fmaf(sc, aw.y, a.y);
            a.z = fmaf(sc, aw.z, a.z);
            a.w = fmaf(sc, aw.w, a.w);
            z_b = fmaf(sc, s_z[w], z_b);
        }
        g_part_acc[c * (DIM / 4) + t] = a;
        if (t == 0) { g_part_m[c] = m_b; g_part_z[c] = z_b; }
        __syncthreads();   // protect s_acc/s_m/s_z before next chunk reuses them
    }
}

// ---------------- phase 2: combine chunk partials per segment, normalize ----------------
__global__ void phase2_kernel(float* __restrict__ out) {
    int b  = blockIdx.x;
    int cs = g_seg_chunk_start[b];
    int cc = g_seg_chunk_cnt[b];
    int t  = threadIdx.x;

    if (cc == 0) {
        ((float4*)out)[b * (DIM / 4) + t] = make_float4(0.f, 0.f, 0.f, 0.f);
        return;
    }

    float m_g = -INFINITY;
    for (int ci = 0; ci < cc; ci++) m_g = fmaxf(m_g, g_part_m[cs + ci]);

    float  z = 0.f;
    float4 a = make_float4(0.f, 0.f, 0.f, 0.f);
    for (int ci = 0; ci < cc; ci++) {
        float sc = __expf(g_part_m[cs + ci] - m_g);
        float4 p = g_part_acc[(cs + ci) * (DIM / 4) + t];
        a.x = fmaf(sc, p.x, a.x);
        a.y = fmaf(sc, p.y, a.y);
        a.z = fmaf(sc, p.z, a.z);
        a.w = fmaf(sc, p.w, a.w);
        z = fmaf(sc, g_part_z[cs + ci], z);
    }
    float inv = 1.f / z;
    ((float4*)out)[b * (DIM / 4) + t] =
        make_float4(a.x * inv, a.y * inv, a.z * inv, a.w * inv);
}

// ---------------- launch ----------------
extern "C" void kernel_launch(void* const* d_in, const int* in_sizes, int n_in,
                              void* d_out, int out_size) {
    // Identify inputs by element count (ordering-proof):
    //   memory_bank 67108864, decoder_state 65536, W 1048576, lens 64.
    const float* mem    = nullptr;
    const float* dstate = nullptr;
    const float* W      = nullptr;
    const int*   lens   = nullptr;
    for (int i = 0; i < n_in; i++) {
        switch (in_sizes[i]) {
            case 67108864: mem    = (const float*)d_in[i]; break;
            case 65536:    dstate = (const float*)d_in[i]; break;
            case 1048576:  W      = (const float*)d_in[i]; break;
            case 64:       lens   = (const int*)d_in[i];   break;
        }
    }
    float* out = (float*)d_out;

    setup_kernel<<<1, BATCH>>>(lens);
    vproj_kernel<<<dim3(4, 4, NSPLIT), 256>>>(dstate, W);
    vreduce_kernel<<<256, 256>>>();
    phase1_kernel<<<P1_GRID, 256>>>(mem);
    phase2_kernel<<<BATCH, 256>>>(out);
}

// round 6
// speedup vs baseline: 1.2847x; 1.0572x over previous
#include <cuda_runtime.h>
#include <math.h>

#define BATCH 64
#define NTOT  65536
#define DIM   1024
#define CHUNK 64
#define MAX_CHUNKS 1088   // NTOT/CHUNK + BATCH
#define NSPLIT 16
#define P1_GRID 296       // 2 CTAs per SM on 148 SMs

// ---------------- device scratch (static, no allocation) ----------------
__device__ float  g_vpart[NSPLIT * BATCH * DIM];
__device__ float  g_v[BATCH * DIM];
__device__ int    g_chunk_seg[MAX_CHUNKS];
__device__ int    g_chunk_start[MAX_CHUNKS];
__device__ int    g_chunk_cnt[MAX_CHUNKS];
__device__ int    g_seg_chunk_start[BATCH];
__device__ int    g_seg_chunk_cnt[BATCH];
__device__ float  g_part_m[MAX_CHUNKS];
__device__ float  g_part_z[MAX_CHUNKS];
__device__ float4 g_part_acc[MAX_CHUNKS * (DIM / 4)];
__device__ int    g_nchunks;
__device__ int    g_next;             // chunk grab counter; reset by K1 each launch
__device__ int    g_tile_done[16];    // split-K arrival counters; self-cleaning
__device__ int    g_seg_done[BATCH];  // per-segment chunk arrival; self-cleaning

// packed f32x2 helpers (sm_103a FFMA2 — PTX-only)
#define FMA2(d, a, b, c) \
    asm("fma.rn.f32x2 %0, %1, %2, %3;" : "=l"(d) : "l"(a), "l"(b), "l"(c))
#define PACK2(out, lo, hi) \
    asm("mov.b64 %0, {%1, %2};" : "=l"(out) : "f"(lo), "f"(hi))

// ============ K1: v-projection (f32x2) + split-K reduce + setup ============
// grid (4 m-tiles, 4 b-tiles, 16 h-splits) = 256 blocks, 256 threads.
__global__ void k1_vproj_setup(const float* __restrict__ dstate,
                               const float* __restrict__ W,
                               const int* __restrict__ lens_raw) {
    __shared__ unsigned long long dsh2[8][64];   // 16 b's packed into 8 f32x2, 64 h
    int m  = blockIdx.x * 256 + threadIdx.x;
    int b0 = blockIdx.y * 16;
    int h0 = blockIdx.z * 64;

    for (int i = threadIdx.x; i < 8 * 64; i += 256) {
        int p = i >> 6, hh = i & 63;
        float lo = dstate[(b0 + 2 * p)     * DIM + h0 + hh];
        float hi = dstate[(b0 + 2 * p + 1) * DIM + h0 + hh];
        unsigned long long pk; PACK2(pk, lo, hi);
        dsh2[p][hh] = pk;
    }
    __syncthreads();

    unsigned long long acc2[8];
#pragma unroll
    for (int i = 0; i < 8; i++) acc2[i] = 0ull;

#pragma unroll 4
    for (int hh = 0; hh < 64; hh++) {
        float w = W[(size_t)(h0 + hh) * DIM + m];
        unsigned long long w2; PACK2(w2, w, w);
#pragma unroll
        for (int i = 0; i < 8; i++) FMA2(acc2[i], dsh2[i][hh], w2, acc2[i]);
    }

    float* outp = g_vpart + (size_t)blockIdx.z * (BATCH * DIM);
#pragma unroll
    for (int i = 0; i < 8; i++) {
        unsigned long long a = acc2[i];
        outp[(b0 + 2 * i)     * DIM + m] = __int_as_float((int)(a & 0xffffffffull));
        outp[(b0 + 2 * i + 1) * DIM + m] = __int_as_float((int)(a >> 32));
    }

    // ---- last z-split for this (bx,by) tile reduces the 16 partials ----
    __shared__ int s_last;
    __threadfence();
    __syncthreads();
    if (threadIdx.x == 0) {
        int old = atomicAdd(&g_tile_done[blockIdx.y * 4 + blockIdx.x], 1);
        s_last = (old == NSPLIT - 1) ? 1 : 0;
        if (blockIdx.z == 0 && blockIdx.x == 0 && blockIdx.y == 0) g_next = 0;
    }
    __syncthreads();
    if (s_last) {
        __threadfence();   // acquire: make all splits' writes visible
        for (int i = threadIdx.x; i < 16 * 256; i += 256) {
            int bl = i >> 8, mm = i & 255;
            int b = blockIdx.y * 16 + bl;
            int mc = blockIdx.x * 256 + mm;
            float s = 0.f;
#pragma unroll
            for (int p = 0; p < NSPLIT; p++)
                s += g_vpart[(size_t)p * BATCH * DIM + b * DIM + mc];
            g_v[b * DIM + mc] = s;
        }
        if (threadIdx.x == 0)
            g_tile_done[blockIdx.y * 4 + blockIdx.x] = 0;   // self-clean for next launch
    }

    // ---- setup (chunk table) in block (0,0,0) — independent side task ----
    if (blockIdx.x == 0 && blockIdx.y == 0 && blockIdx.z == 0) {
        __shared__ int s_len[BATCH], s_noff[BATCH], s_coff[BATCH];
        int b = threadIdx.x;
        const long long* lens64 = (const long long*)lens_raw;
        bool is64 = (lens_raw[1] == 0);   // int64 LE high word of elem0 is 0
        if (b < BATCH) s_len[b] = is64 ? (int)lens64[b] : lens_raw[b];
        __syncthreads();
        if (b == 0) {
            int noff = 0, coff = 0;
            for (int i = 0; i < BATCH; i++) {
                s_noff[i] = noff; s_coff[i] = coff;
                noff += s_len[i];
                coff += (s_len[i] + CHUNK - 1) / CHUNK;
            }
            g_nchunks = coff;
        }
        __syncthreads();
        if (b < BATCH) {
            int len = s_len[b];
            int nck = (len + CHUNK - 1) / CHUNK;
            int cs  = s_coff[b];
            g_seg_chunk_start[b] = cs;
            g_seg_chunk_cnt[b]   = nck;
            for (int k = 0; k < nck; k++) {
                g_chunk_seg[cs + k]   = b;
                g_chunk_start[cs + k] = s_noff[b] + k * CHUNK;
                int rem = len - k * CHUNK;
                g_chunk_cnt[cs + k]   = rem < CHUNK ? rem : CHUNK;
            }
        }
    }
}

// ============ K2: streaming online-softmax + fused final combine ============
// Persistent CTAs grab chunks via atomic counter. Warp-per-node; lane owns
// 32 elements (8 x float4). Last chunk of a segment performs the segment's
// final combine + normalize (deterministic: fixed read order).
__global__ void __launch_bounds__(256, 2) k2_phase1(const float* __restrict__ mem,
                                                    float* __restrict__ out) {
    __shared__ float4 s_acc[8][256];   // 32 KB per-warp accumulators
    __shared__ float  s_m[8], s_z[8];
    __shared__ int    s_c, s_last;

    int warp = threadIdx.x >> 5;
    int lane = threadIdx.x & 31;
    int t    = threadIdx.x;
    int nchunks = g_nchunks;

    while (true) {
        if (t == 0) s_c = atomicAdd(&g_next, 1);
        __syncthreads();
        int c = s_c;
        if (c >= nchunks) break;

        int cnt   = g_chunk_cnt[c];
        int seg   = g_chunk_seg[c];
        int start = g_chunk_start[c];

        // v row for this segment (L2-hot), register-resident
        const float4* vp = (const float4*)(g_v + seg * DIM);
        float4 v[8];
#pragma unroll
        for (int j = 0; j < 8; j++) v[j] = vp[j * 32 + lane];

        float m = -INFINITY, z = 0.f;
        float4 acc[8];
#pragma unroll
        for (int j = 0; j < 8; j++) acc[j] = make_float4(0.f, 0.f, 0.f, 0.f);

        for (int i = warp; i < cnt; i += 8) {
            const float4* row = (const float4*)(mem + (size_t)(start + i) * DIM);
            float4 r[8];
#pragma unroll
            for (int j = 0; j < 8; j++) r[j] = __ldcs(row + j * 32 + lane);

            float s = 0.f;
#pragma unroll
            for (int j = 0; j < 8; j++)
                s += r[j].x * v[j].x + r[j].y * v[j].y + r[j].z * v[j].z + r[j].w * v[j].w;
#pragma unroll
            for (int o = 16; o > 0; o >>= 1) s += __shfl_xor_sync(0xffffffffu, s, o);

            if (s > m) {
                float sc = __expf(m - s);   // exp(-inf)=0 handles first node
                z = z * sc + 1.f;
#pragma unroll
                for (int j = 0; j < 8; j++) {
                    acc[j].x = acc[j].x * sc + r[j].x;
                    acc[j].y = acc[j].y * sc + r[j].y;
                    acc[j].z = acc[j].z * sc + r[j].z;
                    acc[j].w = acc[j].w * sc + r[j].w;
                }
                m = s;
            } else {
                float w8 = __expf(s - m);
                z += w8;
#pragma unroll
                for (int j = 0; j < 8; j++) {
                    acc[j].x = fmaf(w8, r[j].x, acc[j].x);
                    acc[j].y = fmaf(w8, r[j].y, acc[j].y);
                    acc[j].z = fmaf(w8, r[j].z, acc[j].z);
                    acc[j].w = fmaf(w8, r[j].w, acc[j].w);
                }
            }
        }

        // combine 8 warp-local accumulators -> chunk partial
#pragma unroll
        for (int j = 0; j < 8; j++) s_acc[warp][j * 32 + lane] = acc[j];
        if (lane == 0) { s_m[warp] = m; s_z[warp] = z; }
        __syncthreads();

        float m_b = -INFINITY;
#pragma unroll
        for (int w = 0; w < 8; w++) m_b = fmaxf(m_b, s_m[w]);

        float  z_b = 0.f;
        float4 a   = make_float4(0.f, 0.f, 0.f, 0.f);
#pragma unroll
        for (int w = 0; w < 8; w++) {
            float mw = s_m[w];
            float sc = (mw == -INFINITY) ? 0.f : __expf(mw - m_b);  // idle warp -> 0
            float4 aw = s_acc[w][t];
            a.x = fmaf(sc, aw.x, a.x);
            a.y = fmaf(sc, aw.y, a.y);
            a.z = fmaf(sc, aw.z, a.z);
            a.w = fmaf(sc, aw.w, a.w);
            z_b = fmaf(sc, s_z[w], z_b);
        }
        g_part_acc[c * (DIM / 4) + t] = a;
        if (t == 0) { g_part_m[c] = m_b; g_part_z[c] = z_b; }

        // ---- publish partial; last chunk of this segment does the combine ----
        __threadfence();
        __syncthreads();   // all partial writes done before the arrival atomic
        if (t == 0) {
            int old = atomicAdd(&g_seg_done[seg], 1);
            s_last = (old == g_seg_chunk_cnt[seg] - 1) ? 1 : 0;
        }
        __syncthreads();
        if (s_last) {
            __threadfence();   // acquire: other CTAs' partials now visible
            int cs = g_seg_chunk_start[seg];
            int cc = g_seg_chunk_cnt[seg];

            float m_g = -INFINITY;
            for (int ci = 0; ci < cc; ci++) m_g = fmaxf(m_g, g_part_m[cs + ci]);

            float  zg = 0.f;
            float4 ag = make_float4(0.f, 0.f, 0.f, 0.f);
            for (int ci = 0; ci < cc; ci++) {
                float sc = __expf(g_part_m[cs + ci] - m_g);
                float4 p = g_part_acc[(cs + ci) * (DIM / 4) + t];
                ag.x = fmaf(sc, p.x, ag.x);
                ag.y = fmaf(sc, p.y, ag.y);
                ag.z = fmaf(sc, p.z, ag.z);
                ag.w = fmaf(sc, p.w, ag.w);
                zg = fmaf(sc, g_part_z[cs + ci], zg);
            }
            float inv = 1.f / zg;
            ((float4*)out)[seg * (DIM / 4) + t] =
                make_float4(ag.x * inv, ag.y * inv, ag.z * inv, ag.w * inv);
            if (t == 0) g_seg_done[seg] = 0;   // self-clean for next launch
        }
        __syncthreads();   // protect shared buffers before next chunk
    }
}

// ---------------- launch ----------------
extern "C" void kernel_launch(void* const* d_in, const int* in_sizes, int n_in,
                              void* d_out, int out_size) {
    // Identify inputs by element count (ordering-proof):
    //   memory_bank 67108864, decoder_state 65536, W 1048576, lens 64.
    const float* mem    = nullptr;
    const float* dstate = nullptr;
    const float* W      = nullptr;
    const int*   lens   = nullptr;
    for (int i = 0; i < n_in; i++) {
        switch (in_sizes[i]) {
            case 67108864: mem    = (const float*)d_in[i]; break;
            case 65536:    dstate = (const float*)d_in[i]; break;
            case 1048576:  W      = (const float*)d_in[i]; break;
            case 64:       lens   = (const int*)d_in[i];   break;
        }
    }
    float* out = (float*)d_out;

    k1_vproj_setup<<<dim3(4, 4, NSPLIT), 256>>>(dstate, W, lens);
    k2_phase1<<<P1_GRID, 256>>>(mem, out);
}